// round 8
// baseline (speedup 1.0000x reference)
#include <cuda_runtime.h>
#include <cstdint>

#define N_ATOMS 100000
#define N_ATOMS_PAD 102400   // multiple of 4096 for the scan
#define N_EDGES 400000
#define N_MOLS  4096
#define ATOM_FDIM 133
#define BOND_FDIM 14
#define HIDDEN 300
#define N_LABELS 12
#define NPAD 320        // padded hidden width
#define KX 144          // padded atom feature dim (multiple of 16)
#define KE 16           // padded bond feature dim
#define KH 304          // padded hidden as K-dim (multiple of 16)

#define BM 128
#define BN 160
#define BK 16
#define AS_STRIDE 20    // floats; banks (20*fr+fc)%32 all-distinct
#define BS_STRIDE2 164  // float2; (fc*164+fr) mod 16 == fc*4+fr -> both LDS.64 phases conflict-free

// ------------------------- scratch (static, no allocs) -------------------------
__device__ float g_xpad[(size_t)N_ATOMS * KX];
__device__ float g_hv  [(size_t)N_ATOMS * NPAD];
__device__ float g_hv2 [(size_t)N_ATOMS * NPAD];
__device__ float g_P   [(size_t)N_ATOMS * NPAD];
__device__ float g_agg [(size_t)N_ATOMS * NPAD];
__device__ float g_mol [(size_t)N_MOLS * NPAD];
__device__ float g_ffn [(size_t)N_MOLS * NPAD];

// packed-pair weights: row r=(k/8)*4+fc holds float2(W[k0+fc][n], W[k0+fc+4][n])
__device__ float g_atomWp[KX * NPAD];
__device__ float g_WiTopp[KH * NPAD];
__device__ float g_Wop   [2 * KH * NPAD];
__device__ float g_ffn1p [KH * NPAD];
__device__ float g_WiBot [KE * NPAD];     // row-major [14+pad][320] for gather
__device__ float g_atomB[NPAD];
__device__ float g_WoB  [NPAD];
__device__ float g_ffn1B[NPAD];
__device__ float g_zeros[NPAD];   // stays zero

// CSR scratch
__device__ int g_counts[N_ATOMS_PAD];
__device__ int g_rowptr[N_ATOMS_PAD + 1];
__device__ int g_cursor[N_ATOMS];
__device__ int g_esrc[N_EDGES];
__device__ int g_eid [N_EDGES];
__device__ int g_molptr[N_MOLS + 1];
__device__ float g_eacsr[(size_t)N_EDGES * 16];   // edge_attr permuted to CSR order, padded to 16

// ------------------------- helpers -------------------------
__device__ __forceinline__ float tf32r(float x) {
    asm("cvt.rna.tf32.f32 %0, %0;" : "+f"(x));
    return x;
}
__device__ __forceinline__ uint32_t smem_u32(const void* p) {
    return (uint32_t)__cvta_generic_to_shared(p);
}

// ------------------------- repack: zero-padded copy (+optional tf32 round) ------------
__global__ void repack(float* __restrict__ dst, const float* __restrict__ src,
                       int dstR, int dstC, int srcR, int srcC, int srcRow0, int doRound) {
    int idx = blockIdx.x * blockDim.x + threadIdx.x;
    if (idx >= dstR * dstC) return;
    int r = idx / dstC, c = idx - r * dstC;
    float v = 0.f;
    if (r < srcR && c < srcC) v = src[(size_t)(r + srcRow0) * srcC + c];
    dst[idx] = doRound ? tf32r(v) : v;
}

// packed-pair weight repack: dst row (k/8)*4+fc, element n = (W[k][n], W[k+4][n]) tf32-rounded
__global__ void repackP(float2* __restrict__ dst, const float* __restrict__ src,
                        int Ktot, int kValid, int srcC, int srcRow0) {
    int idx = blockIdx.x * blockDim.x + threadIdx.x;
    int total = (Ktot >> 3) * 4 * NPAD;
    if (idx >= total) return;
    int row = idx / NPAD, n = idx - row * NPAD;
    int kb = row >> 2, fc = row & 3;
    int klo = kb * 8 + fc, khi = klo + 4;
    float vlo = 0.f, vhi = 0.f;
    if (klo < kValid && n < srcC) vlo = tf32r(src[(size_t)(klo + srcRow0) * srcC + n]);
    if (khi < kValid && n < srcC) vhi = tf32r(src[(size_t)(khi + srcRow0) * srcC + n]);
    dst[idx] = make_float2(vlo, vhi);
}

__global__ void zeroI(int* __restrict__ p, int n) {
    int i = blockIdx.x * blockDim.x + threadIdx.x;
    if (i < n) p[i] = 0;
}

// ------------------------- CSR build -------------------------
__global__ void hist_dst(const int* __restrict__ dst, int* __restrict__ counts) {
    int e = blockIdx.x * blockDim.x + threadIdx.x;
    if (e < N_EDGES) atomicAdd(&counts[dst[e]], 1);
}

__global__ __launch_bounds__(1024)
void scan_counts(const int* __restrict__ counts, int* __restrict__ rowptr) {
    __shared__ int warp_sums[32];
    __shared__ int s_carry;
    const int tid = threadIdx.x;
    const int lane = tid & 31, wid = tid >> 5;
    if (tid == 0) s_carry = 0;
    __syncthreads();
    for (int base = 0; base < N_ATOMS_PAD; base += 4096) {
        int4 v = *(const int4*)(counts + base + tid * 4);
        int tsum = v.x + v.y + v.z + v.w;
        int val = tsum;
        #pragma unroll
        for (int off = 1; off < 32; off <<= 1) {
            int t = __shfl_up_sync(~0u, val, off);
            if (lane >= off) val += t;
        }
        if (lane == 31) warp_sums[wid] = val;
        __syncthreads();
        if (wid == 0) {
            int w = warp_sums[lane];
            #pragma unroll
            for (int off = 1; off < 32; off <<= 1) {
                int t = __shfl_up_sync(~0u, w, off);
                if (lane >= off) w += t;
            }
            warp_sums[lane] = w;
        }
        __syncthreads();
        int carry = s_carry;
        int excl = carry + (wid ? warp_sums[wid - 1] : 0) + (val - tsum);
        int idx = base + tid * 4;
        rowptr[idx + 0] = excl;
        rowptr[idx + 1] = excl + v.x;
        rowptr[idx + 2] = excl + v.x + v.y;
        rowptr[idx + 3] = excl + v.x + v.y + v.z;
        __syncthreads();
        if (tid == 0) s_carry = carry + warp_sums[31];
        __syncthreads();
    }
    if (threadIdx.x == 0) rowptr[N_ATOMS_PAD] = s_carry;
}

__global__ void copy_cursor(const int* __restrict__ rowptr, int* __restrict__ cursor) {
    int i = blockIdx.x * blockDim.x + threadIdx.x;
    if (i < N_ATOMS) cursor[i] = rowptr[i];
}

__global__ void fill_csr(const int* __restrict__ src, const int* __restrict__ dst,
                         int* __restrict__ cursor,
                         int* __restrict__ esrc, int* __restrict__ eid) {
    int e = blockIdx.x * blockDim.x + threadIdx.x;
    if (e >= N_EDGES) return;
    int d = dst[e];
    int pos = atomicAdd(&cursor[d], 1);
    esrc[pos] = src[e];
    eid[pos]  = e;
}

// permute edge_attr into CSR order (padded to 16 floats/row)
__global__ void permute_ea(const float* __restrict__ ea, const int* __restrict__ eid,
                           float* __restrict__ eacsr) {
    int idx = blockIdx.x * blockDim.x + threadIdx.x;
    if (idx >= N_EDGES * 16) return;
    int p = idx >> 4, c = idx & 15;
    float v = 0.f;
    if (c < BOND_FDIM) v = ea[(size_t)eid[p] * BOND_FDIM + c];
    eacsr[idx] = v;
}

__global__ void build_molptr(const int* __restrict__ batch, int* __restrict__ molptr) {
    int i = blockIdx.x * blockDim.x + threadIdx.x;
    if (i >= N_ATOMS) return;
    int b = batch[i];
    int bp = (i == 0) ? -1 : batch[i - 1];
    for (int m = bp + 1; m <= b; m++) molptr[m] = i;
    if (i == N_ATOMS - 1)
        for (int m = b + 1; m <= N_MOLS; m++) molptr[m] = N_ATOMS;
}

// ------------------------- tf32 tensor-core GEMM -------------------------
// C[M x 320] = round_tf32(relu?(A @ W + bias)).
// A = virtual concat of A1 (K1 cols) and A2 (K2 cols); inputs pre-rounded.
// W in packed-pair layout Wp (float2 rows of NPAD).
// Block tile 128x160, BK=16, cp.async double-buffered.
// 8 warps in 2(m) x 4(n); warp tile 64x40 (4 m16-tiles x 5 n8-tiles).
__global__ __launch_bounds__(256)
void gemm_tf32(const float* __restrict__ A1, int lda1, int K1,
               const float* __restrict__ A2, int lda2, int K2,
               const float2* __restrict__ Wp, const float* __restrict__ bias,
               float* __restrict__ C, int M, int doRelu) {
    __shared__ float  As[2][BM][AS_STRIDE];        // m-major
    __shared__ float2 Bs[2][8][BS_STRIDE2];        // packed k-pairs, rows = ks*4+fc

    const int tid  = threadIdx.x;
    const int lane = tid & 31;
    const int wid  = tid >> 5;
    const int wm0  = (wid >> 2) * 64;   // 0,64
    const int wn0  = (wid & 3) * 40;    // 0,40,80,120
    const int row0 = blockIdx.x * BM;
    const int n0   = blockIdx.y * BN;
    const int fr = lane >> 2;
    const int fc = lane & 3;
    const int Ktot = K1 + K2;
    const int niter = Ktot / BK;

    float acc[4][5][4];
    #pragma unroll
    for (int mt = 0; mt < 4; mt++)
        #pragma unroll
        for (int nt = 0; nt < 5; nt++)
            #pragma unroll
            for (int i = 0; i < 4; i++) acc[mt][nt][i] = 0.f;

    // ---- async staging of tile k0 into buffer buf ----
    auto stage = [&](int k0, int buf) {
        const float* Asrc; int lda, kb;
        if (k0 < K1) { Asrc = A1; lda = lda1; kb = k0; }
        else         { Asrc = A2; lda = lda2; kb = k0 - K1; }
        // A tile: 128 rows x 16 k = 512 16B-chunks, 2 per thread
        #pragma unroll
        for (int j = 0; j < 2; j++) {
            int chunk = tid + j * 256;
            int m = chunk >> 2, kq = (chunk & 3) << 2;
            int g = row0 + m;
            const float* src = Asrc + (size_t)g * lda + kb + kq;
            uint32_t dst = smem_u32(&As[buf][m][kq]);
            int ss = (g < M) ? 16 : 0;
            asm volatile("cp.async.cg.shared.global [%0], [%1], 16, %2;"
                         :: "r"(dst), "l"(src), "r"(ss));
        }
        // B tile (packed): 8 rows x 160 float2 = 640 16B-chunks
        #pragma unroll
        for (int j = 0; j < 3; j++) {
            int chunk = tid + j * 256;
            if (chunk < 640) {
                int rp = chunk / 80, col2 = (chunk - rp * 80) << 1;
                const float2* src = Wp + (size_t)((k0 >> 3) * 4 + rp) * NPAD + n0 + col2;
                uint32_t dst = smem_u32(&Bs[buf][rp][col2]);
                asm volatile("cp.async.cg.shared.global [%0], [%1], 16;"
                             :: "r"(dst), "l"(src));
            }
        }
        asm volatile("cp.async.commit_group;");
    };

    stage(0, 0);

    for (int it = 0; it < niter; it++) {
        int buf = it & 1;
        bool more = (it + 1 < niter);
        if (more) stage((it + 1) * BK, buf ^ 1);
        if (more) asm volatile("cp.async.wait_group 1;");
        else      asm volatile("cp.async.wait_group 0;");
        __syncthreads();

        #pragma unroll
        for (int ks = 0; ks < 2; ks++) {
            const int kk = ks * 8;
            uint32_t a[4][4], b[5][2];
            #pragma unroll
            for (int mt = 0; mt < 4; mt++) {
                int mr = wm0 + mt * 16 + fr;
                a[mt][0] = __float_as_uint(As[buf][mr][kk + fc]);
                a[mt][1] = __float_as_uint(As[buf][mr + 8][kk + fc]);
                a[mt][2] = __float_as_uint(As[buf][mr][kk + fc + 4]);
                a[mt][3] = __float_as_uint(As[buf][mr + 8][kk + fc + 4]);
            }
            #pragma unroll
            for (int nt = 0; nt < 5; nt++) {
                int nc = wn0 + nt * 8 + fr;
                float2 bv = Bs[buf][ks * 4 + fc][nc];
                b[nt][0] = __float_as_uint(bv.x);
                b[nt][1] = __float_as_uint(bv.y);
            }
            #pragma unroll
            for (int mt = 0; mt < 4; mt++)
                #pragma unroll
                for (int nt = 0; nt < 5; nt++)
                    asm volatile(
                        "mma.sync.aligned.m16n8k8.row.col.f32.tf32.tf32.f32 "
                        "{%0,%1,%2,%3}, {%4,%5,%6,%7}, {%8,%9}, {%0,%1,%2,%3};"
                        : "+f"(acc[mt][nt][0]), "+f"(acc[mt][nt][1]),
                          "+f"(acc[mt][nt][2]), "+f"(acc[mt][nt][3])
                        : "r"(a[mt][0]), "r"(a[mt][1]), "r"(a[mt][2]), "r"(a[mt][3]),
                          "r"(b[nt][0]), "r"(b[nt][1]));
        }
        __syncthreads();
    }

    // epilogue: bias + relu? + tf32 round
    #pragma unroll
    for (int mt = 0; mt < 4; mt++) {
        int r = row0 + wm0 + mt * 16 + fr;
        #pragma unroll
        for (int nt = 0; nt < 5; nt++) {
            int cbase = n0 + wn0 + nt * 8 + (fc << 1);
            float2 bv = *(const float2*)&bias[cbase];
            if (r < M) {
                float2 v = make_float2(acc[mt][nt][0] + bv.x, acc[mt][nt][1] + bv.y);
                if (doRelu) { v.x = fmaxf(v.x, 0.f); v.y = fmaxf(v.y, 0.f); }
                v.x = tf32r(v.x); v.y = tf32r(v.y);
                *(float2*)(C + (size_t)r * NPAD + cbase) = v;
            }
            if (r + 8 < M) {
                float2 v = make_float2(acc[mt][nt][2] + bv.x, acc[mt][nt][3] + bv.y);
                if (doRelu) { v.x = fmaxf(v.x, 0.f); v.y = fmaxf(v.y, 0.f); }
                v.x = tf32r(v.x); v.y = tf32r(v.y);
                *(float2*)(C + (size_t)(r + 8) * NPAD + cbase) = v;
            }
        }
    }
}

// ------------------------- CSR gather: agg[v] = sum_in relu(P[src] + eacsr[p] @ WiBot) -----
__global__ __launch_bounds__(256)
void gather_agg(const float* __restrict__ P, const float* __restrict__ eacsr,
                const float* __restrict__ WiBot,
                const int* __restrict__ rowptr, const int* __restrict__ esrc,
                float* __restrict__ agg) {
    __shared__ float Ws[14 * NPAD];
    for (int i = threadIdx.x; i < 14 * NPAD; i += 256) Ws[i] = WiBot[i];
    __syncthreads();

    int v = (blockIdx.x * 256 + threadIdx.x) >> 5;
    int lane = threadIdx.x & 31;
    if (v >= N_ATOMS) return;
    int beg = rowptr[v], end = rowptr[v + 1];

    float acc[10];
    #pragma unroll
    for (int j = 0; j < 10; j++) acc[j] = 0.f;

    for (int p = beg; p < end; p++) {
        int s = esrc[p];
        float eav = (lane < 16) ? eacsr[(size_t)p * 16 + lane] : 0.f;
        float ef[14];
        #pragma unroll
        for (int f = 0; f < 14; f++) ef[f] = __shfl_sync(~0u, eav, f);
        const float* Pr = P + (size_t)s * NPAD;
        #pragma unroll
        for (int j = 0; j < 10; j++) {
            float m = Pr[lane + 32 * j];
            #pragma unroll
            for (int f = 0; f < 14; f++)
                m = fmaf(ef[f], Ws[f * NPAD + lane + 32 * j], m);
            acc[j] += fmaxf(m, 0.f);
        }
    }
    float* ag = agg + (size_t)v * NPAD;
    #pragma unroll
    for (int j = 0; j < 10; j++) ag[lane + 32 * j] = tf32r(acc[j]);
}

// ------------------------- molecule pooling (contiguous ranges) -------
__global__ void mol_sum(const float* __restrict__ hv, const int* __restrict__ molptr,
                        float* __restrict__ mol) {
    int m = (blockIdx.x * blockDim.x + threadIdx.x) >> 5;
    int lane = threadIdx.x & 31;
    if (m >= N_MOLS) return;
    int beg = molptr[m], end = molptr[m + 1];
    float acc[10];
    #pragma unroll
    for (int j = 0; j < 10; j++) acc[j] = 0.f;
    for (int a = beg; a < end; a++) {
        const float* hr = hv + (size_t)a * NPAD;
        #pragma unroll
        for (int j = 0; j < 10; j++) acc[j] += hr[lane + 32 * j];
    }
    float* mr = mol + (size_t)m * NPAD;
    #pragma unroll
    for (int j = 0; j < 10; j++) mr[lane + 32 * j] = tf32r(acc[j]);
}

// ------------------------- final: out = ffn @ ffn2 + b2 -------------------------
__global__ void finalk(const float* __restrict__ F, const float* __restrict__ W2,
                       const float* __restrict__ b2, float* __restrict__ out) {
    int w = (blockIdx.x * blockDim.x + threadIdx.x) >> 5;
    int lane = threadIdx.x & 31;
    if (w >= N_MOLS) return;
    float acc = (lane < 12) ? b2[lane] : 0.f;
    const float* f = F + (size_t)w * NPAD;
    for (int j = 0; j < HIDDEN; j++) {
        float fv = __ldg(f + j);
        if (lane < 12) acc = fmaf(fv, W2[j * 12 + lane], acc);
    }
    if (lane < 12) out[w * 12 + lane] = acc;
}

// ------------------------- host launch -------------------------
static inline dim3 rep_grid(int n) { return dim3((n + 255) / 256); }

extern "C" void kernel_launch(void* const* d_in, const int* in_sizes, int n_in,
                              void* d_out, int out_size) {
    const float* x      = (const float*)d_in[0];
    const int*   ei     = (const int*)  d_in[1];   // [2, N_EDGES]
    const float* ea     = (const float*)d_in[2];
    const int*   batch  = (const int*)  d_in[3];
    const float* atom_W = (const float*)d_in[4];
    const float* atom_b = (const float*)d_in[5];
    // d_in[6], d_in[7]: bond_W / bond_b  -> dead code
    const float* Wi     = (const float*)d_in[8];
    // d_in[9]: Wh -> dead code
    const float* Wo     = (const float*)d_in[10];
    const float* Wo_b   = (const float*)d_in[11];
    const float* ffn1_W = (const float*)d_in[12];
    const float* ffn1_b = (const float*)d_in[13];
    const float* ffn2_W = (const float*)d_in[14];
    const float* ffn2_b = (const float*)d_in[15];
    float* out = (float*)d_out;

    float *p_xpad, *p_hv, *p_hv2, *p_P, *p_agg, *p_mol, *p_ffn;
    float *p_atomWp, *p_WiTopp, *p_Wop, *p_ffn1p, *p_WiBot;
    float *p_atomB, *p_WoB, *p_ffn1B, *p_zeros, *p_eacsr;
    int *p_counts, *p_rowptr, *p_cursor, *p_esrc, *p_eid, *p_molptr;
    cudaGetSymbolAddress((void**)&p_xpad,  g_xpad);
    cudaGetSymbolAddress((void**)&p_hv,    g_hv);
    cudaGetSymbolAddress((void**)&p_hv2,   g_hv2);
    cudaGetSymbolAddress((void**)&p_P,     g_P);
    cudaGetSymbolAddress((void**)&p_agg,   g_agg);
    cudaGetSymbolAddress((void**)&p_mol,   g_mol);
    cudaGetSymbolAddress((void**)&p_ffn,   g_ffn);
    cudaGetSymbolAddress((void**)&p_atomWp, g_atomWp);
    cudaGetSymbolAddress((void**)&p_WiTopp, g_WiTopp);
    cudaGetSymbolAddress((void**)&p_Wop,    g_Wop);
    cudaGetSymbolAddress((void**)&p_ffn1p,  g_ffn1p);
    cudaGetSymbolAddress((void**)&p_WiBot,  g_WiBot);
    cudaGetSymbolAddress((void**)&p_atomB, g_atomB);
    cudaGetSymbolAddress((void**)&p_WoB,   g_WoB);
    cudaGetSymbolAddress((void**)&p_ffn1B, g_ffn1B);
    cudaGetSymbolAddress((void**)&p_zeros, g_zeros);
    cudaGetSymbolAddress((void**)&p_eacsr, g_eacsr);
    cudaGetSymbolAddress((void**)&p_counts, g_counts);
    cudaGetSymbolAddress((void**)&p_rowptr, g_rowptr);
    cudaGetSymbolAddress((void**)&p_cursor, g_cursor);
    cudaGetSymbolAddress((void**)&p_esrc,   g_esrc);
    cudaGetSymbolAddress((void**)&p_eid,    g_eid);
    cudaGetSymbolAddress((void**)&p_molptr, g_molptr);

    const int* e_src = ei;
    const int* e_dst = ei + N_EDGES;

    // ---- repack inputs / weights (x pre-rounded; weights packed-pair + pre-rounded) ----
    repack<<<rep_grid(N_ATOMS * KX), 256>>>(p_xpad, x, N_ATOMS, KX, N_ATOMS, ATOM_FDIM, 0, 1);
    repackP<<<rep_grid(KX / 2 * NPAD), 256>>>((float2*)p_atomWp, atom_W, KX, ATOM_FDIM, HIDDEN, 0);
    repackP<<<rep_grid(KH / 2 * NPAD), 256>>>((float2*)p_WiTopp, Wi, KH, HIDDEN, HIDDEN, 0);
    repackP<<<rep_grid(KH / 2 * NPAD), 256>>>((float2*)p_Wop, Wo, KH, HIDDEN, HIDDEN, 0);
    repackP<<<rep_grid(KH / 2 * NPAD), 256>>>((float2*)p_Wop + (KH / 8) * 4 * NPAD, Wo,
                                              KH, HIDDEN, HIDDEN, HIDDEN);
    repackP<<<rep_grid(KH / 2 * NPAD), 256>>>((float2*)p_ffn1p, ffn1_W, KH, HIDDEN, HIDDEN, 0);
    repack<<<rep_grid(KE * NPAD), 256>>>(p_WiBot, Wi, KE, NPAD, BOND_FDIM, HIDDEN, HIDDEN, 1);
    repack<<<rep_grid(NPAD), 256>>>(p_atomB, atom_b, 1, NPAD, 1, HIDDEN, 0, 0);
    repack<<<rep_grid(NPAD), 256>>>(p_WoB, Wo_b, 1, NPAD, 1, HIDDEN, 0, 0);
    repack<<<rep_grid(NPAD), 256>>>(p_ffn1B, ffn1_b, 1, NPAD, 1, HIDDEN, 0, 0);

    // ---- CSR build (by dst) + ea permute + mol boundaries ----
    zeroI<<<rep_grid(N_ATOMS_PAD), 256>>>(p_counts, N_ATOMS_PAD);
    hist_dst<<<rep_grid(N_EDGES), 256>>>(e_dst, p_counts);
    scan_counts<<<1, 1024>>>(p_counts, p_rowptr);
    copy_cursor<<<rep_grid(N_ATOMS), 256>>>(p_rowptr, p_cursor);
    fill_csr<<<rep_grid(N_EDGES), 256>>>(e_src, e_dst, p_cursor, p_esrc, p_eid);
    permute_ea<<<rep_grid(N_EDGES * 16), 256>>>(ea, p_eid, p_eacsr);
    build_molptr<<<rep_grid(N_ATOMS), 256>>>(batch, p_molptr);

    dim3 gAtom((N_ATOMS + BM - 1) / BM, NPAD / BN);
    dim3 gMol ((N_MOLS  + BM - 1) / BM, NPAD / BN);

    // h_v = relu(x @ atom_W + atom_b)
    gemm_tf32<<<gAtom, 256>>>(p_xpad, KX, KX, nullptr, 0, 0,
                              (const float2*)p_atomWp, p_atomB, p_hv, N_ATOMS, 1);

    int gather_blocks = (N_ATOMS * 32 + 255) / 256;

    float* cur = p_hv;
    float* nxt = p_hv2;
    for (int d = 0; d < 3; d++) {
        // P = h_v @ Wi_top
        gemm_tf32<<<gAtom, 256>>>(cur, NPAD, KH, nullptr, 0, 0,
                                  (const float2*)p_WiTopp, p_zeros, p_P, N_ATOMS, 0);
        // agg[v] = sum over in-edges of relu(P[src] + edge_attr @ WiBot)
        gather_agg<<<gather_blocks, 256>>>(p_P, p_eacsr, p_WiBot, p_rowptr, p_esrc, p_agg);
        // h_v = relu([h_v, agg] @ Wo + Wo_b)
        gemm_tf32<<<gAtom, 256>>>(cur, NPAD, KH, p_agg, NPAD, KH,
                                  (const float2*)p_Wop, p_WoB, nxt, N_ATOMS, 1);
        float* t = cur; cur = nxt; nxt = t;
    }

    // mol_repr = segment_sum(h_v, batch)
    mol_sum<<<(N_MOLS * 32 + 255) / 256, 256>>>(cur, p_molptr, p_mol);
    // ffn = relu(mol @ ffn1 + b1)
    gemm_tf32<<<gMol, 256>>>(p_mol, NPAD, KH, nullptr, 0, 0,
                             (const float2*)p_ffn1p, p_ffn1B, p_ffn, N_MOLS, 1);
    // out = ffn @ ffn2 + b2
    finalk<<<(N_MOLS * 32 + 255) / 256, 256>>>(p_ffn, ffn2_W, ffn2_b, out);
}